// round 2
// baseline (speedup 1.0000x reference)
#include <cuda_runtime.h>
#include <cuda_bf16.h>
#include <math.h>

// Problem shape
#define BB 8
#define TT 2048
#define CC 1024
#define HH 16
#define DD 64
#define MTOT (BB*TT)      // 16384
#define KDIM 1024
#define N_QKV 3072
#define N_PROJ 1024

// Scratch (allocation-free rule: __device__ globals)
__device__ float g_qkv[(size_t)MTOT * N_QKV];      // 192 MB: holds phi_q | phi_k*mask | v*mask after epilogue
__device__ float g_y  [(size_t)MTOT * CC];         // 64 MB
__device__ float g_kv [(size_t)BB*HH*DD*DD];       // 2 MB
__device__ float g_ks [(size_t)BB*HH*DD];          // 32 KB

// ---------------------------------------------------------------------------
// Tiled fp32 GEMM: C[M,N] = A[M,1024] * B[1024,N] + bias, optional qkv epilogue
// Block tile 128x128, 256 threads, 8x8 per-thread microtile, K-step 16.
// EPI==0: qkv epilogue (phi on cols<2048, mask on cols>=1024). EPI==1: bias only.
// ---------------------------------------------------------------------------
template<int EPI>
__global__ __launch_bounds__(256, 2)
void gemm128(const float* __restrict__ A, const float* __restrict__ Bm,
             const float* __restrict__ bias, const int* __restrict__ am,
             float* __restrict__ Cout, int N)
{
    __shared__ float As[16][128];
    __shared__ float Bs[16][128];

    const int tid = threadIdx.x;
    const int bm = blockIdx.y * 128;
    const int bn = blockIdx.x * 128;

    const int tm = (tid >> 4) * 8;   // 0..120
    const int tn = (tid & 15) * 8;   // 0..120

    float c[8][8];
#pragma unroll
    for (int i = 0; i < 8; i++)
#pragma unroll
        for (int j = 0; j < 8; j++) c[i][j] = 0.f;

    const int arow = tid >> 2;          // 0..63
    const int acol = (tid & 3) * 4;     // 0,4,8,12
    const int brow = tid >> 5;          // 0..7
    const int bcol = (tid & 31) * 4;    // 0..124

    for (int k0 = 0; k0 < KDIM; k0 += 16) {
        // Load A tile (128 x 16), store transposed As[k][m]
#pragma unroll
        for (int i = 0; i < 2; i++) {
            int r = arow + i * 64;
            float4 va = *(const float4*)(A + (size_t)(bm + r) * KDIM + k0 + acol);
            As[acol + 0][r] = va.x;
            As[acol + 1][r] = va.y;
            As[acol + 2][r] = va.z;
            As[acol + 3][r] = va.w;
        }
        // Load B tile (16 x 128)
#pragma unroll
        for (int i = 0; i < 2; i++) {
            int r = brow + i * 8;
            *(float4*)&Bs[r][bcol] =
                *(const float4*)(Bm + (size_t)(k0 + r) * N + bn + bcol);
        }
        __syncthreads();

#pragma unroll
        for (int kk = 0; kk < 16; kk++) {
            float4 a0 = *(float4*)&As[kk][tm];
            float4 a1 = *(float4*)&As[kk][tm + 4];
            float4 b0 = *(float4*)&Bs[kk][tn];
            float4 b1 = *(float4*)&Bs[kk][tn + 4];
            float af[8] = {a0.x, a0.y, a0.z, a0.w, a1.x, a1.y, a1.z, a1.w};
            float bf[8] = {b0.x, b0.y, b0.z, b0.w, b1.x, b1.y, b1.z, b1.w};
#pragma unroll
            for (int i = 0; i < 8; i++)
#pragma unroll
                for (int j = 0; j < 8; j++)
                    c[i][j] = fmaf(af[i], bf[j], c[i][j]);
        }
        __syncthreads();
    }

    // Epilogue + store
    const int col0 = bn + tn;
    float bvals[8];
#pragma unroll
    for (int j = 0; j < 8; j++) bvals[j] = bias[col0 + j];

#pragma unroll
    for (int i = 0; i < 8; i++) {
        int row = bm + tm + i;
        float mv = 1.f;
        if (EPI == 0) mv = (am[row] > 0) ? 1.f : 0.f;
        float o[8];
#pragma unroll
        for (int j = 0; j < 8; j++) {
            int col = col0 + j;
            float v = c[i][j] + bvals[j];
            if (EPI == 0) {
                if (col < 2048) v = (v > 0.f) ? (v + 1.f) : expf(v);  // elu+1
                if (col >= 1024) v *= mv;                             // mask k,v
            }
            o[j] = v;
        }
        float* dst = Cout + (size_t)row * N + col0;
        *(float4*)(dst)     = make_float4(o[0], o[1], o[2], o[3]);
        *(float4*)(dst + 4) = make_float4(o[4], o[5], o[6], o[7]);
    }
}

// ---------------------------------------------------------------------------
// K2: per (b,h) -> kv[64,64] = sum_t phi_k[t,:]^T v[t,:] ; ksum[64] = sum_t phi_k
// grid 128, block 256. Each thread owns a 4x4 tile of the 64x64 output.
// ---------------------------------------------------------------------------
__global__ __launch_bounds__(256)
void kv_kernel(const float* __restrict__ qkv, float* __restrict__ kvout,
               float* __restrict__ ksout)
{
    __shared__ float ks[16][64];
    __shared__ float vs[16][64];

    const int bh = blockIdx.x;
    const int b = bh >> 4, h = bh & 15;
    const int tid = threadIdx.x;

    const float* kb = qkv + (size_t)b * TT * N_QKV + 1024 + h * DD;
    const float* vb = kb + 1024;

    const int lr  = tid >> 4;          // 0..15 (t within chunk)
    const int lc4 = (tid & 15) * 4;    // 0..60 (d)
    const int i0  = (tid >> 4) * 4;    // d rows of kv
    const int j0  = (tid & 15) * 4;    // f cols of kv

    float acc[4][4];
#pragma unroll
    for (int i = 0; i < 4; i++)
#pragma unroll
        for (int j = 0; j < 4; j++) acc[i][j] = 0.f;
    float ksum4[4] = {0.f, 0.f, 0.f, 0.f};
    const bool owns_ksum = ((tid & 15) == 0);

    for (int t0 = 0; t0 < TT; t0 += 16) {
        size_t off = (size_t)(t0 + lr) * N_QKV + lc4;
        *(float4*)&ks[lr][lc4] = *(const float4*)(kb + off);
        *(float4*)&vs[lr][lc4] = *(const float4*)(vb + off);
        __syncthreads();
#pragma unroll
        for (int t = 0; t < 16; t++) {
            float4 k4 = *(float4*)&ks[t][i0];
            float4 v4 = *(float4*)&vs[t][j0];
            float ka[4] = {k4.x, k4.y, k4.z, k4.w};
            float va[4] = {v4.x, v4.y, v4.z, v4.w};
#pragma unroll
            for (int i = 0; i < 4; i++)
#pragma unroll
                for (int j = 0; j < 4; j++)
                    acc[i][j] = fmaf(ka[i], va[j], acc[i][j]);
            if (owns_ksum) {
#pragma unroll
                for (int i = 0; i < 4; i++) ksum4[i] += ka[i];
            }
        }
        __syncthreads();
    }

    float* kvdst = kvout + (size_t)bh * DD * DD;
#pragma unroll
    for (int i = 0; i < 4; i++) {
        *(float4*)&kvdst[(i0 + i) * DD + j0] =
            make_float4(acc[i][0], acc[i][1], acc[i][2], acc[i][3]);
    }
    if (owns_ksum) {
#pragma unroll
        for (int i = 0; i < 4; i++) ksout[bh * DD + i0 + i] = ksum4[i];
    }
}

// ---------------------------------------------------------------------------
// K3: y[t,f] = (phi_q[t,:] . kv[:,f]) / max(phi_q[t,:] . ksum, 1e-8)
// grid (16, 128): 128 t-rows per block per (b,h). 2 threads per row (32 f each).
// ---------------------------------------------------------------------------
__global__ __launch_bounds__(256)
void y_kernel(const float* __restrict__ qkv, const float* __restrict__ kv,
              const float* __restrict__ ksum, float* __restrict__ y)
{
    __shared__ float kvs[DD * DD];   // 16 KB
    __shared__ float kss[DD];

    const int bh = blockIdx.y;
    const int b = bh >> 4, h = bh & 15;
    const int tid = threadIdx.x;

    const float4* kvsrc = (const float4*)(kv + (size_t)bh * DD * DD);
#pragma unroll
    for (int i = 0; i < 4; i++)
        ((float4*)kvs)[tid + i * 256] = kvsrc[tid + i * 256];
    if (tid < DD) kss[tid] = ksum[bh * DD + tid];
    __syncthreads();

    const int t = blockIdx.x * 128 + (tid >> 1);
    const int f0 = (tid & 1) * 32;
    const float* qrow = qkv + (size_t)(b * TT + t) * N_QKV + h * DD;  // phi_q

    float acc[32];
#pragma unroll
    for (int f = 0; f < 32; f++) acc[f] = 0.f;
    float den = 0.f;

#pragma unroll 4
    for (int d4 = 0; d4 < 16; d4++) {
        float4 q4 = *(const float4*)(qrow + d4 * 4);
        float qa[4] = {q4.x, q4.y, q4.z, q4.w};
#pragma unroll
        for (int u = 0; u < 4; u++) {
            int d = d4 * 4 + u;
            den = fmaf(qa[u], kss[d], den);
            const float* kr = &kvs[d * DD + f0];
#pragma unroll
            for (int f = 0; f < 32; f += 4) {
                float4 kv4 = *(const float4*)(kr + f);
                acc[f]     = fmaf(qa[u], kv4.x, acc[f]);
                acc[f + 1] = fmaf(qa[u], kv4.y, acc[f + 1]);
                acc[f + 2] = fmaf(qa[u], kv4.z, acc[f + 2]);
                acc[f + 3] = fmaf(qa[u], kv4.w, acc[f + 3]);
            }
        }
    }

    const float inv = 1.f / fmaxf(den, 1e-8f);
    float* yd = y + (size_t)(b * TT + t) * CC + h * DD + f0;
#pragma unroll
    for (int f = 0; f < 32; f += 4) {
        *(float4*)(yd + f) = make_float4(acc[f] * inv, acc[f + 1] * inv,
                                         acc[f + 2] * inv, acc[f + 3] * inv);
    }
}

// ---------------------------------------------------------------------------
extern "C" void kernel_launch(void* const* d_in, const int* in_sizes, int n_in,
                              void* d_out, int out_size)
{
    const float* x      = (const float*)d_in[0];
    const int*   am     = (const int*)  d_in[1];
    const float* w_attn = (const float*)d_in[2];
    const float* b_attn = (const float*)d_in[3];
    const float* w_proj = (const float*)d_in[4];
    const float* b_proj = (const float*)d_in[5];
    float* out = (float*)d_out;

    float *qkv, *yb, *kvb, *ksb;
    cudaGetSymbolAddress((void**)&qkv, g_qkv);
    cudaGetSymbolAddress((void**)&yb,  g_y);
    cudaGetSymbolAddress((void**)&kvb, g_kv);
    cudaGetSymbolAddress((void**)&ksb, g_ks);

    // K1: qkv = x @ w_attn + b_attn, fused phi/mask epilogue
    gemm128<0><<<dim3(N_QKV / 128, MTOT / 128), 256>>>(x, w_attn, b_attn, am, qkv, N_QKV);
    // K2: per-head kv state + ksum
    kv_kernel<<<BB * HH, 256>>>(qkv, kvb, ksb);
    // K3: normalized linear attention output -> y [MTOT, 1024]
    y_kernel<<<dim3(TT / 128, BB * HH), 256>>>(qkv, kvb, ksb, yb);
    // K4: out = y @ w_proj + b_proj
    gemm128<1><<<dim3(N_PROJ / 128, MTOT / 128), 256>>>(yb, w_proj, b_proj, nullptr, out, N_PROJ);
}

// round 4
// speedup vs baseline: 2.1608x; 2.1608x over previous
#include <cuda_runtime.h>
#include <cuda_bf16.h>
#include <math.h>
#include <stdint.h>

// Problem shape
#define BB 8
#define TT 2048
#define CC 1024
#define HH 16
#define DD 64
#define MTOT (BB*TT)      // 16384
#define KDIM 1024
#define N_QKV 3072
#define N_PROJ 1024

// ---------------- scratch (__device__ globals; no allocation allowed) -------
__device__ float         g_qkv [(size_t)MTOT * N_QKV];   // phi_q | phi_k*m | v*m
__device__ __nv_bfloat16 g_xhi [(size_t)MTOT * KDIM];
__device__ __nv_bfloat16 g_xlo [(size_t)MTOT * KDIM];
__device__ __nv_bfloat16 g_wahi[(size_t)N_QKV * KDIM];   // transposed [N,K]
__device__ __nv_bfloat16 g_walo[(size_t)N_QKV * KDIM];
__device__ __nv_bfloat16 g_wphi[(size_t)N_PROJ * KDIM];
__device__ __nv_bfloat16 g_wplo[(size_t)N_PROJ * KDIM];
__device__ __nv_bfloat16 g_yhi [(size_t)MTOT * CC];
__device__ __nv_bfloat16 g_ylo [(size_t)MTOT * CC];
__device__ float g_kvp[8 * BB*HH * DD*DD];
__device__ float g_ksp[8 * BB*HH * DD];
__device__ float g_kv [BB*HH * DD*DD];
__device__ float g_ks [BB*HH * DD];

// ---------------- helpers ----------------------------------------------------
__device__ __forceinline__ uint32_t smem_u32(const void* p) {
    uint32_t a;
    asm("{ .reg .u64 t; cvta.to.shared.u64 t, %1; cvt.u32.u64 %0, t; }"
        : "=r"(a) : "l"(p));
    return a;
}
__device__ __forceinline__ void cpasync16(uint32_t dst, const void* src) {
    asm volatile("cp.async.cg.shared.global [%0], [%1], 16;" :: "r"(dst), "l"(src));
}
#define CP_COMMIT() asm volatile("cp.async.commit_group;" ::: "memory")
#define CP_WAIT2()  asm volatile("cp.async.wait_group 2;" ::: "memory")

__device__ __forceinline__ void ldsm4(uint32_t (&r)[4], uint32_t addr) {
    asm volatile("ldmatrix.sync.aligned.m8n8.x4.shared.b16 {%0,%1,%2,%3}, [%4];"
                 : "=r"(r[0]), "=r"(r[1]), "=r"(r[2]), "=r"(r[3]) : "r"(addr));
}
__device__ __forceinline__ void mma16816(float (&c)[4], const uint32_t (&a)[4],
                                         uint32_t b0, uint32_t b1) {
    asm volatile(
        "mma.sync.aligned.m16n8k16.row.col.f32.bf16.bf16.f32 "
        "{%0,%1,%2,%3}, {%4,%5,%6,%7}, {%8,%9}, {%0,%1,%2,%3};"
        : "+f"(c[0]), "+f"(c[1]), "+f"(c[2]), "+f"(c[3])
        : "r"(a[0]), "r"(a[1]), "r"(a[2]), "r"(a[3]), "r"(b0), "r"(b1));
}

__device__ __forceinline__ void split2(float v, __nv_bfloat16& h, __nv_bfloat16& l) {
    h = __float2bfloat16(v);
    l = __float2bfloat16(v - __bfloat162float(h));
}

// ---------------- conversion kernels ----------------------------------------
__global__ __launch_bounds__(256)
void split_x_kernel(const float4* __restrict__ in, uint2* __restrict__ hi,
                    uint2* __restrict__ lo) {
    size_t i = (size_t)blockIdx.x * blockDim.x + threadIdx.x;
    float4 v = in[i];
    __nv_bfloat16 h0, h1, h2, h3, l0, l1, l2, l3;
    split2(v.x, h0, l0); split2(v.y, h1, l1);
    split2(v.z, h2, l2); split2(v.w, h3, l3);
    uint32_t ha = (uint32_t)__bfloat16_as_ushort(h0) | ((uint32_t)__bfloat16_as_ushort(h1) << 16);
    uint32_t hb = (uint32_t)__bfloat16_as_ushort(h2) | ((uint32_t)__bfloat16_as_ushort(h3) << 16);
    uint32_t la = (uint32_t)__bfloat16_as_ushort(l0) | ((uint32_t)__bfloat16_as_ushort(l1) << 16);
    uint32_t lb = (uint32_t)__bfloat16_as_ushort(l2) | ((uint32_t)__bfloat16_as_ushort(l3) << 16);
    hi[i] = make_uint2(ha, hb);
    lo[i] = make_uint2(la, lb);
}

// w [K,N] row-major -> hi/lo [N,K] (K-major), split to bf16
__global__ __launch_bounds__(256)
void transpose_split_kernel(const float* __restrict__ w, __nv_bfloat16* __restrict__ hi,
                            __nv_bfloat16* __restrict__ lo, int K, int N) {
    __shared__ float t[32][33];
    int n0 = blockIdx.x * 32, k0 = blockIdx.y * 32;
    int tx = threadIdx.x, ty = threadIdx.y;
#pragma unroll
    for (int i = 0; i < 4; i++)
        t[ty + i * 8][tx] = w[(size_t)(k0 + ty + i * 8) * N + n0 + tx];
    __syncthreads();
#pragma unroll
    for (int i = 0; i < 4; i++) {
        float v = t[tx][ty + i * 8];
        __nv_bfloat16 h, l;
        split2(v, h, l);
        size_t o = (size_t)(n0 + ty + i * 8) * K + k0 + tx;
        hi[o] = h; lo[o] = l;
    }
}

// ---------------- mma.sync split-bf16 GEMM ----------------------------------
// C[M,N] (fp32) = A[M,K] * B[N,K]^T + bias. A/B as bf16 hi+lo (3-term emulation).
// Block: 128x128, BK=32, 4-stage cp.async pipeline, 8 warps (2 rows x 4 cols),
// warp tile 64x32. EPI==0: qkv epilogue. EPI==1: bias only.
#define BKG 32
#define RSTRIDE 40                 // smem row stride in bf16 elems (80 B, 20-bank skew)
#define OP_BYTES (128 * RSTRIDE * 2)   // 10240 per operand tile
#define STG_BYTES (4 * OP_BYTES)       // Ahi|Alo|Bhi|Blo = 40960
#define NSTG 4
#define GSMEM (NSTG * STG_BYTES)       // 163840

template<int EPI>
__global__ __launch_bounds__(256, 1)
void mgemm(const __nv_bfloat16* __restrict__ Ahi, const __nv_bfloat16* __restrict__ Alo,
           const __nv_bfloat16* __restrict__ Bhi, const __nv_bfloat16* __restrict__ Blo,
           const float* __restrict__ bias, const int* __restrict__ am,
           float* __restrict__ Cout, int N)
{
    extern __shared__ char smem_raw[];
    const uint32_t sbase = smem_u32(smem_raw);
    const int tid = threadIdx.x;
    const int wid = tid >> 5, lane = tid & 31;
    const int warp_row = wid & 1;        // 0..1  (64 rows each)
    const int warp_col = wid >> 1;       // 0..3  (32 cols each)
    const int bm = blockIdx.y * 128;
    const int bn = blockIdx.x * 128;

    float acc[4][4][4];                  // [m-tile][n-tile][frag]
#pragma unroll
    for (int i = 0; i < 4; i++)
#pragma unroll
        for (int j = 0; j < 4; j++)
#pragma unroll
            for (int q = 0; q < 4; q++) acc[i][j][q] = 0.f;

    // stage loader: 128 rows x 4 chunks(16B) per operand; 512 cp / operand; 2/thread
    auto load_stage = [&](int s) {
        const int k0 = s * BKG;
        const uint32_t sb = sbase + (s % NSTG) * STG_BYTES;
#pragma unroll
        for (int i = 0; i < 2; i++) {
            int c = tid + i * 256;
            int row = c >> 2, ch = c & 3;
            uint32_t so = (uint32_t)row * (RSTRIDE * 2) + ch * 16;
            size_t ga = (size_t)(bm + row) * KDIM + k0 + ch * 8;
            size_t gb = (size_t)(bn + row) * KDIM + k0 + ch * 8;
            cpasync16(sb + 0 * OP_BYTES + so, Ahi + ga);
            cpasync16(sb + 1 * OP_BYTES + so, Alo + ga);
            cpasync16(sb + 2 * OP_BYTES + so, Bhi + gb);
            cpasync16(sb + 3 * OP_BYTES + so, Blo + gb);
        }
        CP_COMMIT();
    };

    const int NS = KDIM / BKG;   // 32
    load_stage(0); load_stage(1); load_stage(2);

    // per-lane ldmatrix address components
    const int a_r = (lane & 7) + 8 * ((lane >> 3) & 1);   // row offset within 16
    const int a_k = 8 * (lane >> 4);                      // k offset 0/8
    const int b_r = (lane & 7) + 8 * (lane >> 4);         // n offset within 16
    const int b_k = 8 * ((lane >> 3) & 1);                // k offset 0/8

    for (int s = 0; s < NS; s++) {
        CP_WAIT2();
        __syncthreads();
        if (s + 3 < NS) load_stage(s + 3);

        const uint32_t sb = sbase + (s % NSTG) * STG_BYTES;
        const uint32_t sAh = sb;
        const uint32_t sAl = sb + OP_BYTES;
        const uint32_t sBh = sb + 2 * OP_BYTES;
        const uint32_t sBl = sb + 3 * OP_BYTES;

#pragma unroll
        for (int kk = 0; kk < 2; kk++) {
            const int kbase = kk * 16;
            uint32_t ah[4][4], al[4][4];
#pragma unroll
            for (int mi = 0; mi < 4; mi++) {
                uint32_t ro = (uint32_t)(warp_row * 64 + mi * 16 + a_r) * (RSTRIDE * 2)
                              + (kbase + a_k) * 2;
                ldsm4(ah[mi], sAh + ro);
                ldsm4(al[mi], sAl + ro);
            }
#pragma unroll
            for (int p = 0; p < 2; p++) {
                uint32_t bo = (uint32_t)(warp_col * 32 + p * 16 + b_r) * (RSTRIDE * 2)
                              + (kbase + b_k) * 2;
                uint32_t bh[4], bl[4];
                ldsm4(bh, sBh + bo);
                ldsm4(bl, sBl + bo);
#pragma unroll
                for (int mi = 0; mi < 4; mi++) {
#pragma unroll
                    for (int j = 0; j < 2; j++) {
                        int ni = 2 * p + j;
                        mma16816(acc[mi][ni], ah[mi], bh[2 * j], bh[2 * j + 1]);
                        mma16816(acc[mi][ni], ah[mi], bl[2 * j], bl[2 * j + 1]);
                        mma16816(acc[mi][ni], al[mi], bh[2 * j], bh[2 * j + 1]);
                    }
                }
            }
        }
    }

    // ---------------- epilogue ----------------
    const int er = lane >> 2;            // 0..7
    const int ec = (lane & 3) * 2;       // 0,2,4,6
#pragma unroll
    for (int mi = 0; mi < 4; mi++) {
#pragma unroll
        for (int half = 0; half < 2; half++) {
            int row = bm + warp_row * 64 + mi * 16 + er + half * 8;
            float mv = 1.f;
            if (EPI == 0) mv = (am[row] > 0) ? 1.f : 0.f;
#pragma unroll
            for (int ni = 0; ni < 4; ni++) {
                int col = bn + warp_col * 32 + ni * 8 + ec;
                float v0 = acc[mi][ni][2 * half]     + bias[col];
                float v1 = acc[mi][ni][2 * half + 1] + bias[col + 1];
                if (EPI == 0) {
                    if (col < 2048) {
                        v0 = (v0 > 0.f) ? (v0 + 1.f) : expf(v0);
                        v1 = (v1 > 0.f) ? (v1 + 1.f) : expf(v1);
                    }
                    if (col >= 1024) { v0 *= mv; v1 *= mv; }
                }
                *(float2*)(Cout + (size_t)row * N + col) = make_float2(v0, v1);
            }
        }
    }
}

// ---------------- K2: per (b,h,chunk) partial kv / ksum ---------------------
__global__ __launch_bounds__(256)
void kv_partial(const float* __restrict__ qkv, float* __restrict__ kvp,
                float* __restrict__ ksp)
{
    __shared__ float ks[16][64];
    __shared__ float vs[16][64];

    const int bh = blockIdx.x >> 3;
    const int chn = blockIdx.x & 7;
    const int b = bh >> 4, h = bh & 15;
    const int tid = threadIdx.x;

    const float* kb = qkv + (size_t)b * TT * N_QKV + 1024 + h * DD;
    const float* vb = kb + 1024;

    const int lr  = tid >> 4;
    const int lc4 = (tid & 15) * 4;
    const int i0  = (tid >> 4) * 4;
    const int j0  = (tid & 15) * 4;

    float acc[4][4];
#pragma unroll
    for (int i = 0; i < 4; i++)
#pragma unroll
        for (int j = 0; j < 4; j++) acc[i][j] = 0.f;
    float ksum4[4] = {0.f, 0.f, 0.f, 0.f};
    const bool owns_ksum = ((tid & 15) == 0);

    const int tbeg = chn * (TT / 8);
    for (int t0 = tbeg; t0 < tbeg + TT / 8; t0 += 16) {
        size_t off = (size_t)(t0 + lr) * N_QKV + lc4;
        *(float4*)&ks[lr][lc4] = *(const float4*)(kb + off);
        *(float4*)&vs[lr][lc4] = *(const float4*)(vb + off);
        __syncthreads();
#pragma unroll
        for (int t = 0; t < 16; t++) {
            float4 k4 = *(float4*)&ks[t][i0];
            float4 v4 = *(float4*)&vs[t][j0];
            float ka[4] = {k4.x, k4.y, k4.z, k4.w};
            float va[4] = {v4.x, v4.y, v4.z, v4.w};
#pragma unroll
            for (int i = 0; i < 4; i++)
#pragma unroll
                for (int j = 0; j < 4; j++)
                    acc[i][j] = fmaf(ka[i], va[j], acc[i][j]);
            if (owns_ksum) {
#pragma unroll
                for (int i = 0; i < 4; i++) ksum4[i] += ka[i];
            }
        }
        __syncthreads();
    }

    float* kvdst = kvp + ((size_t)chn * 128 + bh) * DD * DD;
#pragma unroll
    for (int i = 0; i < 4; i++)
        *(float4*)&kvdst[(i0 + i) * DD + j0] =
            make_float4(acc[i][0], acc[i][1], acc[i][2], acc[i][3]);
    if (owns_ksum) {
#pragma unroll
        for (int i = 0; i < 4; i++)
            ksp[((size_t)chn * 128 + bh) * DD + i0 + i] = ksum4[i];
    }
}

__global__ __launch_bounds__(256)
void kv_reduce(const float* __restrict__ kvp, const float* __restrict__ ksp,
               float* __restrict__ kv, float* __restrict__ ks)
{
    const int bh = blockIdx.x;
    const int tid = threadIdx.x;
    for (int i = tid; i < DD * DD; i += 256) {
        float s = 0.f;
#pragma unroll
        for (int c = 0; c < 8; c++) s += kvp[((size_t)c * 128 + bh) * DD * DD + i];
        kv[(size_t)bh * DD * DD + i] = s;
    }
    if (tid < DD) {
        float s = 0.f;
#pragma unroll
        for (int c = 0; c < 8; c++) s += ksp[((size_t)c * 128 + bh) * DD + tid];
        ks[(size_t)bh * DD + tid] = s;
    }
}

// ---------------- K3: y = (phi_q . kv) / max(phi_q . ksum, eps) -> bf16 hi/lo
__global__ __launch_bounds__(256)
void y_kernel(const float* __restrict__ qkv, const float* __restrict__ kv,
              const float* __restrict__ ksum, __nv_bfloat16* __restrict__ yhi,
              __nv_bfloat16* __restrict__ ylo)
{
    __shared__ float kvs[DD * DD];
    __shared__ float kss[DD];

    const int bh = blockIdx.y;
    const int b = bh >> 4, h = bh & 15;
    const int tid = threadIdx.x;

    const float4* kvsrc = (const float4*)(kv + (size_t)bh * DD * DD);
#pragma unroll
    for (int i = 0; i < 4; i++)
        ((float4*)kvs)[tid + i * 256] = kvsrc[tid + i * 256];
    if (tid < DD) kss[tid] = ksum[bh * DD + tid];
    __syncthreads();

    const int t = blockIdx.x * 128 + (tid >> 1);
    const int f0 = (tid & 1) * 32;
    const float* qrow = qkv + (size_t)(b * TT + t) * N_QKV + h * DD;

    float acc[32];
#pragma unroll
    for (int f = 0; f < 32; f++) acc[f] = 0.f;
    float den = 0.f;

#pragma unroll 4
    for (int d4 = 0; d4 < 16; d4++) {
        float4 q4 = *(const float4*)(qrow + d4 * 4);
        float qa[4] = {q4.x, q4.y, q4.z, q4.w};
#pragma unroll
        for (int u = 0; u < 4; u++) {
            int d = d4 * 4 + u;
            den = fmaf(qa[u], kss[d], den);
            const float* kr = &kvs[d * DD + f0];
#pragma unroll
            for (int f = 0; f < 32; f += 4) {
                float4 kv4 = *(const float4*)(kr + f);
                acc[f]     = fmaf(qa[u], kv4.x, acc[f]);
                acc[f + 1] = fmaf(qa[u], kv4.y, acc[f + 1]);
                acc[f + 2] = fmaf(qa[u], kv4.z, acc[f + 2]);
                acc[f + 3] = fmaf(qa[u], kv4.w, acc[f + 3]);
            }
        }
    }

    const float inv = 1.f / fmaxf(den, 1e-8f);
    const size_t off = (size_t)(b * TT + t) * CC + h * DD + f0;
#pragma unroll
    for (int f = 0; f < 32; f += 8) {
        uint32_t wh[4], wl[4];
#pragma unroll
        for (int j = 0; j < 4; j++) {
            float v0 = acc[f + 2 * j]     * inv;
            float v1 = acc[f + 2 * j + 1] * inv;
            __nv_bfloat16 h0, l0, h1, l1;
            split2(v0, h0, l0);
            split2(v1, h1, l1);
            wh[j] = (uint32_t)__bfloat16_as_ushort(h0) | ((uint32_t)__bfloat16_as_ushort(h1) << 16);
            wl[j] = (uint32_t)__bfloat16_as_ushort(l0) | ((uint32_t)__bfloat16_as_ushort(l1) << 16);
        }
        *(uint4*)(yhi + off + f) = make_uint4(wh[0], wh[1], wh[2], wh[3]);
        *(uint4*)(ylo + off + f) = make_uint4(wl[0], wl[1], wl[2], wl[3]);
    }
}

// ---------------------------------------------------------------------------
extern "C" void kernel_launch(void* const* d_in, const int* in_sizes, int n_in,
                              void* d_out, int out_size)
{
    const float* x      = (const float*)d_in[0];
    const int*   am     = (const int*)  d_in[1];
    const float* w_attn = (const float*)d_in[2];
    const float* b_attn = (const float*)d_in[3];
    const float* w_proj = (const float*)d_in[4];
    const float* b_proj = (const float*)d_in[5];
    float* out = (float*)d_out;

    float *qkv, *kvp, *ksp, *kvb, *ksb;
    __nv_bfloat16 *xhi, *xlo, *wahi, *walo, *wphi, *wplo, *yhi, *ylo;
    cudaGetSymbolAddress((void**)&qkv,  g_qkv);
    cudaGetSymbolAddress((void**)&xhi,  g_xhi);
    cudaGetSymbolAddress((void**)&xlo,  g_xlo);
    cudaGetSymbolAddress((void**)&wahi, g_wahi);
    cudaGetSymbolAddress((void**)&walo, g_walo);
    cudaGetSymbolAddress((void**)&wphi, g_wphi);
    cudaGetSymbolAddress((void**)&wplo, g_wplo);
    cudaGetSymbolAddress((void**)&yhi,  g_yhi);
    cudaGetSymbolAddress((void**)&ylo,  g_ylo);
    cudaGetSymbolAddress((void**)&kvp,  g_kvp);
    cudaGetSymbolAddress((void**)&ksp,  g_ksp);
    cudaGetSymbolAddress((void**)&kvb,  g_kv);
    cudaGetSymbolAddress((void**)&ksb,  g_ks);

    cudaFuncSetAttribute(mgemm<0>, cudaFuncAttributeMaxDynamicSharedMemorySize, GSMEM);
    cudaFuncSetAttribute(mgemm<1>, cudaFuncAttributeMaxDynamicSharedMemorySize, GSMEM);

    // bf16 hi/lo conversions
    split_x_kernel<<<(MTOT * KDIM / 4) / 256, 256>>>((const float4*)x, (uint2*)xhi, (uint2*)xlo);
    transpose_split_kernel<<<dim3(N_QKV / 32, KDIM / 32), dim3(32, 8)>>>(w_attn, wahi, walo, KDIM, N_QKV);
    transpose_split_kernel<<<dim3(N_PROJ / 32, KDIM / 32), dim3(32, 8)>>>(w_proj, wphi, wplo, KDIM, N_PROJ);

    // K1: qkv = x @ w_attn + b_attn (mma.sync), fused phi/mask epilogue
    mgemm<0><<<dim3(N_QKV / 128, MTOT / 128), 256, GSMEM>>>(xhi, xlo, wahi, walo,
                                                            b_attn, am, qkv, N_QKV);
    // K2: per-head kv state + ksum (split over 8 T-chunks, then reduce)
    kv_partial<<<BB * HH * 8, 256>>>(qkv, kvp, ksp);
    kv_reduce<<<BB * HH, 256>>>(kvp, ksp, kvb, ksb);
    // K3: normalized linear attention output -> y (bf16 hi/lo)
    y_kernel<<<dim3(TT / 128, BB * HH), 256>>>(qkv, kvb, ksb, yhi, ylo);
    // K4: out = y @ w_proj + b_proj (mma.sync)
    mgemm<1><<<dim3(N_PROJ / 128, MTOT / 128), 256, GSMEM>>>(yhi, ylo, wphi, wplo,
                                                             b_proj, nullptr, out, N_PROJ);
}

// round 5
// speedup vs baseline: 2.8678x; 1.3272x over previous
#include <cuda_runtime.h>
#include <cuda_bf16.h>
#include <math.h>
#include <stdint.h>

// Problem shape
#define BB 8
#define TT 2048
#define CC 1024
#define HH 16
#define DD 64
#define MTOT (BB*TT)      // 16384
#define KDIM 1024
#define N_QKV 3072
#define N_PROJ 1024

// ---------------- scratch (__device__ globals; no allocation allowed) -------
__device__ float         g_qkv [(size_t)MTOT * N_QKV];   // phi_q | phi_k*m | v*m
__device__ __nv_bfloat16 g_xhi [(size_t)MTOT * KDIM];
__device__ __nv_bfloat16 g_xlo [(size_t)MTOT * KDIM];
__device__ __nv_bfloat16 g_wahi[(size_t)N_QKV * KDIM];   // transposed [N,K]
__device__ __nv_bfloat16 g_walo[(size_t)N_QKV * KDIM];
__device__ __nv_bfloat16 g_wphi[(size_t)N_PROJ * KDIM];
__device__ __nv_bfloat16 g_wplo[(size_t)N_PROJ * KDIM];
__device__ __nv_bfloat16 g_yhi [(size_t)MTOT * CC];
__device__ __nv_bfloat16 g_ylo [(size_t)MTOT * CC];
__device__ float g_kvp[8 * BB*HH * DD*DD];
__device__ float g_ksp[8 * BB*HH * DD];
__device__ float g_kv [BB*HH * DD*DD];
__device__ float g_ks [BB*HH * DD];

// ---------------- helpers ----------------------------------------------------
__device__ __forceinline__ uint32_t smem_u32(const void* p) {
    uint32_t a;
    asm("{ .reg .u64 t; cvta.to.shared.u64 t, %1; cvt.u32.u64 %0, t; }"
        : "=r"(a) : "l"(p));
    return a;
}
__device__ __forceinline__ void cpasync16(uint32_t dst, const void* src) {
    asm volatile("cp.async.cg.shared.global [%0], [%1], 16;" :: "r"(dst), "l"(src));
}
#define CP_COMMIT() asm volatile("cp.async.commit_group;" ::: "memory")
#define CP_WAIT1()  asm volatile("cp.async.wait_group 1;" ::: "memory")

__device__ __forceinline__ void ldsm4(uint32_t (&r)[4], uint32_t addr) {
    asm volatile("ldmatrix.sync.aligned.m8n8.x4.shared.b16 {%0,%1,%2,%3}, [%4];"
                 : "=r"(r[0]), "=r"(r[1]), "=r"(r[2]), "=r"(r[3]) : "r"(addr));
}
__device__ __forceinline__ void mma16816(float (&c)[4], const uint32_t (&a)[4],
                                         uint32_t b0, uint32_t b1) {
    asm volatile(
        "mma.sync.aligned.m16n8k16.row.col.f32.bf16.bf16.f32 "
        "{%0,%1,%2,%3}, {%4,%5,%6,%7}, {%8,%9}, {%0,%1,%2,%3};"
        : "+f"(c[0]), "+f"(c[1]), "+f"(c[2]), "+f"(c[3])
        : "r"(a[0]), "r"(a[1]), "r"(a[2]), "r"(a[3]), "r"(b0), "r"(b1));
}

__device__ __forceinline__ void split2(float v, __nv_bfloat16& h, __nv_bfloat16& l) {
    h = __float2bfloat16(v);
    l = __float2bfloat16(v - __bfloat162float(h));
}

// XOR-swizzled smem offset: 64B rows of 4x16B chunks; chunk ^= (row>>1)&3.
// Conflict-free for cp.async 16B stores and ldmatrix x4 phases (verified:
// 8-row phases hit all 32 banks exactly once).
__device__ __forceinline__ uint32_t swz(int row, int ch) {
    return (uint32_t)((row << 6) + (((ch ^ (row >> 1)) & 3) << 4));
}

// ---------------- conversion kernels ----------------------------------------
__global__ __launch_bounds__(256)
void split_x_kernel(const float4* __restrict__ in, uint2* __restrict__ hi,
                    uint2* __restrict__ lo) {
    size_t i = (size_t)blockIdx.x * blockDim.x + threadIdx.x;
    float4 v = in[i];
    __nv_bfloat16 h0, h1, h2, h3, l0, l1, l2, l3;
    split2(v.x, h0, l0); split2(v.y, h1, l1);
    split2(v.z, h2, l2); split2(v.w, h3, l3);
    uint32_t ha = (uint32_t)__bfloat16_as_ushort(h0) | ((uint32_t)__bfloat16_as_ushort(h1) << 16);
    uint32_t hb = (uint32_t)__bfloat16_as_ushort(h2) | ((uint32_t)__bfloat16_as_ushort(h3) << 16);
    uint32_t la = (uint32_t)__bfloat16_as_ushort(l0) | ((uint32_t)__bfloat16_as_ushort(l1) << 16);
    uint32_t lb = (uint32_t)__bfloat16_as_ushort(l2) | ((uint32_t)__bfloat16_as_ushort(l3) << 16);
    hi[i] = make_uint2(ha, hb);
    lo[i] = make_uint2(la, lb);
}

// w [K,N] row-major -> hi/lo [N,K] (K-major), split to bf16
__global__ __launch_bounds__(256)
void transpose_split_kernel(const float* __restrict__ w, __nv_bfloat16* __restrict__ hi,
                            __nv_bfloat16* __restrict__ lo, int K, int N) {
    __shared__ float t[32][33];
    int n0 = blockIdx.x * 32, k0 = blockIdx.y * 32;
    int tx = threadIdx.x, ty = threadIdx.y;
#pragma unroll
    for (int i = 0; i < 4; i++)
        t[ty + i * 8][tx] = w[(size_t)(k0 + ty + i * 8) * N + n0 + tx];
    __syncthreads();
#pragma unroll
    for (int i = 0; i < 4; i++) {
        float v = t[tx][ty + i * 8];
        __nv_bfloat16 h, l;
        split2(v, h, l);
        size_t o = (size_t)(n0 + ty + i * 8) * K + k0 + tx;
        hi[o] = h; lo[o] = l;
    }
}

// ---------------- mma.sync split-bf16 GEMM ----------------------------------
// C[M,N] (fp32) = A[M,K] * B[N,K]^T + bias. A/B as bf16 hi+lo (3-term emulation).
// Block: 128x128, BK=32, XOR-swizzled smem (32KB/stage), 3 buffers / depth-2
// prefetch, 8 warps (2x4), warp tile 64x32, 2 CTAs/SM.
#define BKG 32
#define OPB (128 * 64)          // 8192 B per operand tile
#define STGB (4 * OPB)          // 32768 B per stage
#define NSTG 3
#define GSMEM (NSTG * STGB)     // 98304 B

template<int EPI>
__global__ __launch_bounds__(256, 2)
void mgemm(const __nv_bfloat16* __restrict__ Ahi, const __nv_bfloat16* __restrict__ Alo,
           const __nv_bfloat16* __restrict__ Bhi, const __nv_bfloat16* __restrict__ Blo,
           const float* __restrict__ bias, const int* __restrict__ am,
           float* __restrict__ Cout, int N)
{
    extern __shared__ char smem_raw[];
    const uint32_t sbase = smem_u32(smem_raw);
    const int tid = threadIdx.x;
    const int wid = tid >> 5, lane = tid & 31;
    const int warp_row = wid & 1;        // 0..1  (64 rows each)
    const int warp_col = wid >> 1;       // 0..3  (32 cols each)
    const int bm = blockIdx.y * 128;
    const int bn = blockIdx.x * 128;

    float acc[4][4][4];                  // [m-tile][n-tile][frag]
#pragma unroll
    for (int i = 0; i < 4; i++)
#pragma unroll
        for (int j = 0; j < 4; j++)
#pragma unroll
            for (int q = 0; q < 4; q++) acc[i][j][q] = 0.f;

    // stage loader: 128 rows x 4 chunks(16B) per operand; 2 rows/thread
    auto load_stage = [&](int s) {
        const int k0 = s * BKG;
        const uint32_t sb = sbase + (s % NSTG) * STGB;
#pragma unroll
        for (int i = 0; i < 2; i++) {
            int c = tid + i * 256;
            int row = c >> 2, ch = c & 3;
            uint32_t so = swz(row, ch);
            size_t ga = (size_t)(bm + row) * KDIM + k0 + ch * 8;
            size_t gb = (size_t)(bn + row) * KDIM + k0 + ch * 8;
            cpasync16(sb + 0 * OPB + so, Ahi + ga);
            cpasync16(sb + 1 * OPB + so, Alo + ga);
            cpasync16(sb + 2 * OPB + so, Bhi + gb);
            cpasync16(sb + 3 * OPB + so, Blo + gb);
        }
        CP_COMMIT();
    };

    const int NS = KDIM / BKG;   // 32
    load_stage(0); load_stage(1);

    // per-lane ldmatrix fragment coordinates
    const int a_r = (lane & 7) + 8 * ((lane >> 3) & 1);   // row offset within 16
    const int a_k = 8 * (lane >> 4);                      // k offset 0/8
    const int b_r = (lane & 7) + 8 * (lane >> 4);         // n offset within 16
    const int b_k = 8 * ((lane >> 3) & 1);                // k offset 0/8

    for (int s = 0; s < NS; s++) {
        CP_WAIT1();
        __syncthreads();
        if (s + 2 < NS) load_stage(s + 2);

        const uint32_t sb = sbase + (s % NSTG) * STGB;

#pragma unroll
        for (int kk = 0; kk < 2; kk++) {
            uint32_t ah[4][4], al[4][4];
#pragma unroll
            for (int mi = 0; mi < 4; mi++) {
                int r = warp_row * 64 + mi * 16 + a_r;
                int ch = (kk * 16 + a_k) >> 3;
                uint32_t ro = swz(r, ch);
                ldsm4(ah[mi], sb + 0 * OPB + ro);
                ldsm4(al[mi], sb + 1 * OPB + ro);
            }
#pragma unroll
            for (int p = 0; p < 2; p++) {
                int rn = warp_col * 32 + p * 16 + b_r;
                int chb = (kk * 16 + b_k) >> 3;
                uint32_t bo = swz(rn, chb);
                uint32_t bh[4], bl[4];
                ldsm4(bh, sb + 2 * OPB + bo);
                ldsm4(bl, sb + 3 * OPB + bo);
                // term-major: 8 independent MMAs per term -> no back-to-back
                // accumulator dependency chains
#pragma unroll
                for (int mi = 0; mi < 4; mi++)
#pragma unroll
                    for (int j = 0; j < 2; j++)
                        mma16816(acc[mi][2 * p + j], ah[mi], bh[2 * j], bh[2 * j + 1]);
#pragma unroll
                for (int mi = 0; mi < 4; mi++)
#pragma unroll
                    for (int j = 0; j < 2; j++)
                        mma16816(acc[mi][2 * p + j], ah[mi], bl[2 * j], bl[2 * j + 1]);
#pragma unroll
                for (int mi = 0; mi < 4; mi++)
#pragma unroll
                    for (int j = 0; j < 2; j++)
                        mma16816(acc[mi][2 * p + j], al[mi], bh[2 * j], bh[2 * j + 1]);
            }
        }
    }

    // ---------------- epilogue ----------------
    const int er = lane >> 2;            // 0..7
    const int ec = (lane & 3) * 2;       // 0,2,4,6
#pragma unroll
    for (int mi = 0; mi < 4; mi++) {
#pragma unroll
        for (int half = 0; half < 2; half++) {
            int row = bm + warp_row * 64 + mi * 16 + er + half * 8;
            float mv = 1.f;
            if (EPI == 0) mv = (am[row] > 0) ? 1.f : 0.f;
#pragma unroll
            for (int ni = 0; ni < 4; ni++) {
                int col = bn + warp_col * 32 + ni * 8 + ec;
                float v0 = acc[mi][ni][2 * half]     + bias[col];
                float v1 = acc[mi][ni][2 * half + 1] + bias[col + 1];
                if (EPI == 0) {
                    if (col < 2048) {
                        v0 = (v0 > 0.f) ? (v0 + 1.f) : expf(v0);
                        v1 = (v1 > 0.f) ? (v1 + 1.f) : expf(v1);
                    }
                    if (col >= 1024) { v0 *= mv; v1 *= mv; }
                }
                *(float2*)(Cout + (size_t)row * N + col) = make_float2(v0, v1);
            }
        }
    }
}

// ---------------- K2: per (b,h,chunk) partial kv / ksum ---------------------
__global__ __launch_bounds__(256)
void kv_partial(const float* __restrict__ qkv, float* __restrict__ kvp,
                float* __restrict__ ksp)
{
    __shared__ float ks[16][64];
    __shared__ float vs[16][64];

    const int bh = blockIdx.x >> 3;
    const int chn = blockIdx.x & 7;
    const int b = bh >> 4, h = bh & 15;
    const int tid = threadIdx.x;

    const float* kb = qkv + (size_t)b * TT * N_QKV + 1024 + h * DD;
    const float* vb = kb + 1024;

    const int lr  = tid >> 4;
    const int lc4 = (tid & 15) * 4;
    const int i0  = (tid >> 4) * 4;
    const int j0  = (tid & 15) * 4;

    float acc[4][4];
#pragma unroll
    for (int i = 0; i < 4; i++)
#pragma unroll
        for (int j = 0; j < 4; j++) acc[i][j] = 0.f;
    float ksum4[4] = {0.f, 0.f, 0.f, 0.f};
    const bool owns_ksum = ((tid & 15) == 0);

    const int tbeg = chn * (TT / 8);
    for (int t0 = tbeg; t0 < tbeg + TT / 8; t0 += 16) {
        size_t off = (size_t)(t0 + lr) * N_QKV + lc4;
        *(float4*)&ks[lr][lc4] = *(const float4*)(kb + off);
        *(float4*)&vs[lr][lc4] = *(const float4*)(vb + off);
        __syncthreads();
#pragma unroll
        for (int t = 0; t < 16; t++) {
            float4 k4 = *(float4*)&ks[t][i0];
            float4 v4 = *(float4*)&vs[t][j0];
            float ka[4] = {k4.x, k4.y, k4.z, k4.w};
            float va[4] = {v4.x, v4.y, v4.z, v4.w};
#pragma unroll
            for (int i = 0; i < 4; i++)
#pragma unroll
                for (int j = 0; j < 4; j++)
                    acc[i][j] = fmaf(ka[i], va[j], acc[i][j]);
            if (owns_ksum) {
#pragma unroll
                for (int i = 0; i < 4; i++) ksum4[i] += ka[i];
            }
        }
        __syncthreads();
    }

    float* kvdst = kvp + ((size_t)chn * 128 + bh) * DD * DD;
#pragma unroll
    for (int i = 0; i < 4; i++)
        *(float4*)&kvdst[(i0 + i) * DD + j0] =
            make_float4(acc[i][0], acc[i][1], acc[i][2], acc[i][3]);
    if (owns_ksum) {
#pragma unroll
        for (int i = 0; i < 4; i++)
            ksp[((size_t)chn * 128 + bh) * DD + i0 + i] = ksum4[i];
    }
}

__global__ __launch_bounds__(256)
void kv_reduce(const float* __restrict__ kvp, const float* __restrict__ ksp,
               float* __restrict__ kv, float* __restrict__ ks)
{
    const int bh = blockIdx.x;
    const int tid = threadIdx.x;
    for (int i = tid; i < DD * DD; i += 256) {
        float s = 0.f;
#pragma unroll
        for (int c = 0; c < 8; c++) s += kvp[((size_t)c * 128 + bh) * DD * DD + i];
        kv[(size_t)bh * DD * DD + i] = s;
    }
    if (tid < DD) {
        float s = 0.f;
#pragma unroll
        for (int c = 0; c < 8; c++) s += ksp[((size_t)c * 128 + bh) * DD + tid];
        ks[(size_t)bh * DD + tid] = s;
    }
}

// ---------------- K3: y = (phi_q . kv) / max(phi_q . ksum, eps) -> bf16 hi/lo
__global__ __launch_bounds__(256)
void y_kernel(const float* __restrict__ qkv, const float* __restrict__ kv,
              const float* __restrict__ ksum, __nv_bfloat16* __restrict__ yhi,
              __nv_bfloat16* __restrict__ ylo)
{
    __shared__ float kvs[DD * DD];
    __shared__ float kss[DD];

    const int bh = blockIdx.y;
    const int b = bh >> 4, h = bh & 15;
    const int tid = threadIdx.x;

    const float4* kvsrc = (const float4*)(kv + (size_t)bh * DD * DD);
#pragma unroll
    for (int i = 0; i < 4; i++)
        ((float4*)kvs)[tid + i * 256] = kvsrc[tid + i * 256];
    if (tid < DD) kss[tid] = ksum[bh * DD + tid];
    __syncthreads();

    const int t = blockIdx.x * 128 + (tid >> 1);
    const int f0 = (tid & 1) * 32;
    const float* qrow = qkv + (size_t)(b * TT + t) * N_QKV + h * DD;

    float acc[32];
#pragma unroll
    for (int f = 0; f < 32; f++) acc[f] = 0.f;
    float den = 0.f;

#pragma unroll 4
    for (int d4 = 0; d4 < 16; d4++) {
        float4 q4 = *(const float4*)(qrow + d4 * 4);
        float qa[4] = {q4.x, q4.y, q4.z, q4.w};
#pragma unroll
        for (int u = 0; u < 4; u++) {
            int d = d4 * 4 + u;
            den = fmaf(qa[u], kss[d], den);
            const float* kr = &kvs[d * DD + f0];
#pragma unroll
            for (int f = 0; f < 32; f += 4) {
                float4 kv4 = *(const float4*)(kr + f);
                acc[f]     = fmaf(qa[u], kv4.x, acc[f]);
                acc[f + 1] = fmaf(qa[u], kv4.y, acc[f + 1]);
                acc[f + 2] = fmaf(qa[u], kv4.z, acc[f + 2]);
                acc[f + 3] = fmaf(qa[u], kv4.w, acc[f + 3]);
            }
        }
    }

    const float inv = 1.f / fmaxf(den, 1e-8f);
    const size_t off = (size_t)(b * TT + t) * CC + h * DD + f0;
#pragma unroll
    for (int f = 0; f < 32; f += 8) {
        uint32_t wh[4], wl[4];
#pragma unroll
        for (int j = 0; j < 4; j++) {
            float v0 = acc[f + 2 * j]     * inv;
            float v1 = acc[f + 2 * j + 1] * inv;
            __nv_bfloat16 h0, l0, h1, l1;
            split2(v0, h0, l0);
            split2(v1, h1, l1);
            wh[j] = (uint32_t)__bfloat16_as_ushort(h0) | ((uint32_t)__bfloat16_as_ushort(h1) << 16);
            wl[j] = (uint32_t)__bfloat16_as_ushort(l0) | ((uint32_t)__bfloat16_as_ushort(l1) << 16);
        }
        *(uint4*)(yhi + off + f) = make_uint4(wh[0], wh[1], wh[2], wh[3]);
        *(uint4*)(ylo + off + f) = make_uint4(wl[0], wl[1], wl[2], wl[3]);
    }
}

// ---------------------------------------------------------------------------
extern "C" void kernel_launch(void* const* d_in, const int* in_sizes, int n_in,
                              void* d_out, int out_size)
{
    const float* x      = (const float*)d_in[0];
    const int*   am     = (const int*)  d_in[1];
    const float* w_attn = (const float*)d_in[2];
    const float* b_attn = (const float*)d_in[3];
    const float* w_proj = (const float*)d_in[4];
    const float* b_proj = (const float*)d_in[5];
    float* out = (float*)d_out;

    float *qkv, *kvp, *ksp, *kvb, *ksb;
    __nv_bfloat16 *xhi, *xlo, *wahi, *walo, *wphi, *wplo, *yhi, *ylo;
    cudaGetSymbolAddress((void**)&qkv,  g_qkv);
    cudaGetSymbolAddress((void**)&xhi,  g_xhi);
    cudaGetSymbolAddress((void**)&xlo,  g_xlo);
    cudaGetSymbolAddress((void**)&wahi, g_wahi);
    cudaGetSymbolAddress((void**)&walo, g_walo);
    cudaGetSymbolAddress((void**)&wphi, g_wphi);
    cudaGetSymbolAddress((void**)&wplo, g_wplo);
    cudaGetSymbolAddress((void**)&yhi,  g_yhi);
    cudaGetSymbolAddress((void**)&ylo,  g_ylo);
    cudaGetSymbolAddress((void**)&kvp,  g_kvp);
    cudaGetSymbolAddress((void**)&ksp,  g_ksp);
    cudaGetSymbolAddress((void**)&kvb,  g_kv);
    cudaGetSymbolAddress((void**)&ksb,  g_ks);

    cudaFuncSetAttribute(mgemm<0>, cudaFuncAttributeMaxDynamicSharedMemorySize, GSMEM);
    cudaFuncSetAttribute(mgemm<1>, cudaFuncAttributeMaxDynamicSharedMemorySize, GSMEM);

    // bf16 hi/lo conversions
    split_x_kernel<<<(MTOT * KDIM / 4) / 256, 256>>>((const float4*)x, (uint2*)xhi, (uint2*)xlo);
    transpose_split_kernel<<<dim3(N_QKV / 32, KDIM / 32), dim3(32, 8)>>>(w_attn, wahi, walo, KDIM, N_QKV);
    transpose_split_kernel<<<dim3(N_PROJ / 32, KDIM / 32), dim3(32, 8)>>>(w_proj, wphi, wplo, KDIM, N_PROJ);

    // K1: qkv = x @ w_attn + b_attn (mma.sync), fused phi/mask epilogue
    mgemm<0><<<dim3(N_QKV / 128, MTOT / 128), 256, GSMEM>>>(xhi, xlo, wahi, walo,
                                                            b_attn, am, qkv, N_QKV);
    // K2: per-head kv state + ksum (split over 8 T-chunks, then reduce)
    kv_partial<<<BB * HH * 8, 256>>>(qkv, kvp, ksp);
    kv_reduce<<<BB * HH, 256>>>(kvp, ksp, kvb, ksb);
    // K3: normalized linear attention output -> y (bf16 hi/lo)
    y_kernel<<<dim3(TT / 128, BB * HH), 256>>>(qkv, kvb, ksb, yhi, ylo);
    // K4: out = y @ w_proj + b_proj (mma.sync)
    mgemm<1><<<dim3(N_PROJ / 128, MTOT / 128), 256, GSMEM>>>(yhi, ylo, wphi, wplo,
                                                             b_proj, nullptr, out, N_PROJ);
}